// round 2
// baseline (speedup 1.0000x reference)
#include <cuda_runtime.h>
#include <cuda_bf16.h>
#include <math.h>

// Problem constants
#define BB 8
#define CC 19
#define HH 512
#define WW 512
#define HW (HH*WW)          // 262144
#define NPLANE 16           // 8 pred-planes + 8 label-planes

// ---------------- device scratch (static, no allocation) ----------------
__device__ unsigned char g_img[NPLANE*HW];     // 4 MB  quantized images
__device__ unsigned char g_state[NPLANE*HW];   // 4 MB  0=none 1=weak 2=strong
__device__ int           g_label[NPLANE*HW];   // 16 MB union-find labels
__device__ unsigned char g_flag[NPLANE*HW];    // 4 MB  component-has-strong (indexed by root)
__device__ int g_pnp[8][BB*WW];                // per-(hchunk) partial column sums
__device__ int g_pnl[8][BB*WW];
__device__ int g_pdt[8][BB*WW];

// ---------------- K1: argmax over C + quantize both images ----------------
// pred [B,C,H,W]: thread handles 4 consecutive pixels (float4 per channel).
__global__ void k_prepare(const float* __restrict__ pred,
                          const float* __restrict__ labels)
{
    int b  = blockIdx.y;
    int i4 = blockIdx.x * blockDim.x + threadIdx.x;   // float4 index in HW/4
    if (i4 >= HW/4) return;

    const float4* base = reinterpret_cast<const float4*>(pred + (size_t)b*CC*HW) + i4;
    float4 best = base[0];
    int bx = 0, by = 0, bz = 0, bw = 0;
    #pragma unroll
    for (int c = 1; c < CC; c++) {
        float4 v = base[(size_t)c * (HW/4)];
        if (v.x > best.x) { best.x = v.x; bx = c; }
        if (v.y > best.y) { best.y = v.y; by = c; }
        if (v.z > best.z) { best.z = v.z; bz = c; }
        if (v.w > best.w) { best.w = v.w; bw = c; }
    }
    // (cls*255) % 256  ==  0 if cls==0 else 256-cls   (cls in 0..18)
    uchar4 op;
    op.x = bx ? (unsigned char)(256 - bx) : 0;
    op.y = by ? (unsigned char)(256 - by) : 0;
    op.z = bz ? (unsigned char)(256 - bz) : 0;
    op.w = bw ? (unsigned char)(256 - bw) : 0;
    reinterpret_cast<uchar4*>(g_img + (size_t)b*HW)[i4] = op;

    float4 l = reinterpret_cast<const float4*>(labels + (size_t)b*HW)[i4];
    uchar4 ol;
    ol.x = (unsigned char)floorf(l.x * 255.0f);
    ol.y = (unsigned char)floorf(l.y * 255.0f);
    ol.z = (unsigned char)floorf(l.z * 255.0f);
    ol.w = (unsigned char)floorf(l.w * 255.0f);
    reinterpret_cast<uchar4*>(g_img + (size_t)(8+b)*HW)[i4] = ol;
}

// ---------------- K2: Sobel + L1 mag + NMS -> state; init labels/flags ----------------
// 32x32 output tile per block. Edge-replicated image halo 2; zero-padded mag halo 1.
__global__ void k_canny()
{
    __shared__ unsigned char simg[36][36];
    __shared__ short         smag[34][36];   // padded cols (conflict-friendly-ish)

    const int plane = blockIdx.z;
    const int oy = blockIdx.y * 32;
    const int ox = blockIdx.x * 32;
    const int tx = threadIdx.x, ty = threadIdx.y;
    const int tid = ty * 32 + tx;
    const unsigned char* img = g_img + (size_t)plane * HW;

    // load 36x36 (edge clamp)
    for (int i = tid; i < 36*36; i += 1024) {
        int sy = i / 36, sx = i % 36;
        int gy = min(max(oy + sy - 2, 0), HH-1);
        int gx = min(max(ox + sx - 2, 0), WW-1);
        simg[sy][sx] = img[gy*WW + gx];
    }
    __syncthreads();

    // mag over 34x34 (zero outside image)
    for (int i = tid; i < 34*34; i += 1024) {
        int sy = i / 34, sx = i % 34;
        int my = oy + sy - 1, mx = ox + sx - 1;
        short m = 0;
        if (my >= 0 && my < HH && mx >= 0 && mx < WW) {
            int a00 = simg[sy  ][sx], a01 = simg[sy  ][sx+1], a02 = simg[sy  ][sx+2];
            int a10 = simg[sy+1][sx],                          a12 = simg[sy+1][sx+2];
            int a20 = simg[sy+2][sx], a21 = simg[sy+2][sx+1], a22 = simg[sy+2][sx+2];
            int gxv = (a02 + 2*a12 + a22) - (a00 + 2*a10 + a20);
            int gyv = (a20 + 2*a21 + a22) - (a00 + 2*a01 + a02);
            m = (short)(abs(gxv) + abs(gyv));
        }
        smag[sy][sx] = m;
    }
    __syncthreads();

    // per-pixel NMS
    const int i1 = ty + 1, j1 = tx + 1;              // smag coords of this pixel
    // recompute own gradient (center simg[ty+2][tx+2])
    int r0 = ty+1, r1 = ty+2, r2 = ty+3, c0 = tx+1, c1 = tx+2, c2 = tx+3;
    int a00 = simg[r0][c0], a01 = simg[r0][c1], a02 = simg[r0][c2];
    int a10 = simg[r1][c0],                     a12 = simg[r1][c2];
    int a20 = simg[r2][c0], a21 = simg[r2][c1], a22 = simg[r2][c2];
    int gxv = (a02 + 2*a12 + a22) - (a00 + 2*a10 + a20);
    int gyv = (a20 + 2*a21 + a22) - (a00 + 2*a01 + a02);
    int m = smag[i1][j1];

    // exact integer direction quantization (ang mod 180, boundaries at tan 22.5/67.5)
    int a = abs(gxv);
    int gyn = gyv, sgx = gxv;
    if (gyn < 0) { gyn = -gyn; sgx = -sgx; }
    int u = gyn + a;
    bool d0  = (u*u < 2*a*a);                 // |tan| < tan22.5
    int v = gyn - a;
    bool lt2 = (v < 0) || (v*v < 2*a*a);      // |tan| < tan67.5

    bool keep;
    if (d0)                   keep = (m >= smag[i1][j1+1]) && (m >= smag[i1][j1-1]);
    else if (sgx > 0 && lt2)  keep = (m >= smag[i1-1][j1+1]) && (m >= smag[i1+1][j1-1]); // 45
    else if (!lt2)            keep = (m >= smag[i1+1][j1]) && (m >= smag[i1-1][j1]);     // 90
    else                      keep = (m >= smag[i1-1][j1-1]) && (m >= smag[i1+1][j1+1]); // 135

    unsigned char st = 0;
    if (keep) { if (m > 200) st = 2; else if (m > 100) st = 1; }

    int gidx = plane*HW + (oy+ty)*WW + (ox+tx);
    g_state[gidx] = st;
    g_label[gidx] = gidx;
    g_flag[gidx]  = 0;
}

// ---------------- union-find helpers ----------------
__device__ __forceinline__ int findroot(int* L, int x)
{
    int p = __ldcg(&L[x]);
    while (p != x) { x = p; p = __ldcg(&L[x]); }
    return x;
}

__device__ __forceinline__ void unite(int* L, int a, int b)
{
    while (true) {
        a = findroot(L, a);
        b = findroot(L, b);
        if (a == b) return;
        if (a < b) { int t = a; a = b; b = t; }   // a > b
        int old = atomicMin(&L[a], b);
        if (old == a) return;
        a = old;
    }
}

// ---------------- K3: merge (8-connectivity among weak pixels) ----------------
__global__ void k_merge()
{
    int idx = blockIdx.x * blockDim.x + threadIdx.x;
    if (idx >= NPLANE*HW) return;
    if (g_state[idx] == 0) return;
    int r = idx & (HW-1);
    int y = r >> 9, x = r & (WW-1);
    if (x > 0            && g_state[idx-1])      unite(g_label, idx, idx-1);
    if (y > 0) {
        if (x > 0        && g_state[idx-WW-1])   unite(g_label, idx, idx-WW-1);
        if (                g_state[idx-WW])     unite(g_label, idx, idx-WW);
        if (x < WW-1     && g_state[idx-WW+1])   unite(g_label, idx, idx-WW+1);
    }
}

// ---------------- K4: flatten + mark strong components ----------------
__global__ void k_flatten()
{
    int idx = blockIdx.x * blockDim.x + threadIdx.x;
    if (idx >= NPLANE*HW) return;
    int root = findroot(g_label, idx);
    g_label[idx] = root;
    if (g_state[idx] == 2) g_flag[root] = 1;
}

// ---------------- K5: per-column partial sums (n_p, n_l, dot) ----------------
__global__ void k_part()
{
    int b  = blockIdx.y;          // batch
    int hc = blockIdx.x;          // h-chunk of 64 rows
    int w  = threadIdx.x;         // 512 threads = one per column
    int np = 0, nl = 0, dt = 0;
    int base_p = b*HW       + hc*64*WW + w;
    int base_l = (8+b)*HW   + hc*64*WW + w;
    #pragma unroll 4
    for (int hh = 0; hh < 64; hh++) {
        int ip = base_p + hh*WW;
        int il = base_l + hh*WW;
        int e1 = (g_state[ip] && g_flag[g_label[ip]]) ? 1 : 0;
        int e2 = (g_state[il] && g_flag[g_label[il]]) ? 1 : 0;
        np += e1; nl += e2; dt += (e1 & e2);
    }
    int col = b*WW + w;
    g_pnp[hc][col] = np;
    g_pnl[hc][col] = nl;
    g_pdt[hc][col] = dt;
}

// ---------------- K6: final scalar (single block, deterministic) ----------------
__global__ void k_final(float* __restrict__ out)
{
    __shared__ float red[1024];
    float acc = 0.0f;
    for (int col = threadIdx.x; col < BB*WW; col += 1024) {
        int np = 0, nl = 0, dt = 0;
        #pragma unroll
        for (int hc = 0; hc < 8; hc++) {
            np += g_pnp[hc][col];
            nl += g_pnl[hc][col];
            dt += g_pdt[hc][col];
        }
        // logsumexp of a 512-column with np ones: log(512 + np*(e-1))
        float lse = logf(fmaf((float)np, 1.7182818284590452f, 512.0f));
        acc += (float)nl * lse - (float)dt;
    }
    red[threadIdx.x] = acc;
    __syncthreads();
    for (int s = 512; s > 0; s >>= 1) {
        if (threadIdx.x < s) red[threadIdx.x] += red[threadIdx.x + s];
        __syncthreads();
    }
    if (threadIdx.x == 0) out[0] = red[0] * (1.0f / (float)(BB*WW));
}

// ---------------- launch ----------------
extern "C" void kernel_launch(void* const* d_in, const int* in_sizes, int n_in,
                              void* d_out, int out_size)
{
    const float* pred   = (const float*)d_in[0];
    const float* labels = (const float*)d_in[1];
    // robustness: identify by element count if order differs
    if (n_in >= 2 && in_sizes[0] == BB*HW && in_sizes[1] == BB*CC*HW) {
        pred   = (const float*)d_in[1];
        labels = (const float*)d_in[0];
    }
    float* out = (float*)d_out;

    k_prepare<<<dim3(HW/4/256, BB), 256>>>(pred, labels);
    k_canny  <<<dim3(WW/32, HH/32, NPLANE), dim3(32, 32)>>>();
    k_merge  <<<(NPLANE*HW)/256, 256>>>();
    k_flatten<<<(NPLANE*HW)/256, 256>>>();
    k_part   <<<dim3(8, BB), 512>>>();
    k_final  <<<1, 1024>>>(out);
}

// round 4
// speedup vs baseline: 1.1732x; 1.1732x over previous
#include <cuda_runtime.h>
#include <cuda_bf16.h>
#include <math.h>

// Problem constants
#define BB 8
#define CC 19
#define HH 512
#define WW 512
#define HW (HH*WW)          // 262144
#define NPLANE 16           // 8 pred-planes + 8 label-planes
#define NHC 16              // h-chunks in k_part

// ---------------- device scratch (static, no allocation) ----------------
__device__ unsigned char g_img[NPLANE*HW];     // 4 MB  quantized images
__device__ unsigned char g_state[NPLANE*HW];   // 4 MB  0=none 1=weak 2=strong
__device__ int           g_label[NPLANE*HW];   // 16 MB union-find labels (only valid where state>0)
__device__ unsigned char g_flag[NPLANE*HW];    // 4 MB  component-has-strong (indexed by root)
__device__ int g_pnp[NHC][BB*WW];              // per-(hchunk) partial column sums
__device__ int g_pnl[NHC][BB*WW];
__device__ int g_pdt[NHC][BB*WW];

// ---------------- K1: argmax over C + quantize both images ----------------
__global__ void k_prepare(const float* __restrict__ pred,
                          const float* __restrict__ labels)
{
    int b  = blockIdx.y;
    int i4 = blockIdx.x * blockDim.x + threadIdx.x;   // float4 index in HW/4
    if (i4 >= HW/4) return;

    const float4* base = reinterpret_cast<const float4*>(pred + (size_t)b*CC*HW) + i4;
    float4 best = base[0];
    int bx = 0, by = 0, bz = 0, bw = 0;
    #pragma unroll
    for (int c = 1; c < CC; c++) {
        float4 v = base[(size_t)c * (HW/4)];
        if (v.x > best.x) { best.x = v.x; bx = c; }
        if (v.y > best.y) { best.y = v.y; by = c; }
        if (v.z > best.z) { best.z = v.z; bz = c; }
        if (v.w > best.w) { best.w = v.w; bw = c; }
    }
    // (cls*255) % 256  ==  0 if cls==0 else 256-cls   (cls in 0..18)
    uchar4 op;
    op.x = bx ? (unsigned char)(256 - bx) : 0;
    op.y = by ? (unsigned char)(256 - by) : 0;
    op.z = bz ? (unsigned char)(256 - bz) : 0;
    op.w = bw ? (unsigned char)(256 - bw) : 0;
    reinterpret_cast<uchar4*>(g_img + (size_t)b*HW)[i4] = op;

    float4 l = reinterpret_cast<const float4*>(labels + (size_t)b*HW)[i4];
    uchar4 ol;
    ol.x = (unsigned char)floorf(l.x * 255.0f);
    ol.y = (unsigned char)floorf(l.y * 255.0f);
    ol.z = (unsigned char)floorf(l.z * 255.0f);
    ol.w = (unsigned char)floorf(l.w * 255.0f);
    reinterpret_cast<uchar4*>(g_img + (size_t)(8+b)*HW)[i4] = ol;
}

// ---------------- smem union-find helpers (tile-local CCL) ----------------
__device__ __forceinline__ int findrootS(volatile int* L, int x)
{
    int p = L[x];
    while (p != x) { x = p; p = L[x]; }
    return x;
}

__device__ __forceinline__ void uniteS(volatile int* L, int a, int b)
{
    while (true) {
        a = findrootS(L, a);
        b = findrootS(L, b);
        if (a == b) return;
        if (a < b) { int t = a; a = b; b = t; }   // a > b
        int old = atomicMin((int*)&L[a], b);
        if (old == a) return;
        a = old;
    }
}

// ---------------- K2: Sobel + NMS + tile-local union-find ----------------
// 32x32 output tile per block (1024 threads, one pixel each).
__global__ void k_canny()
{
    __shared__ unsigned char simg[36][36];
    __shared__ short         smag[34][36];
    __shared__ unsigned char sst[32][32];
    __shared__ int           sl[1024];

    const int plane = blockIdx.z;
    const int oy = blockIdx.y * 32;
    const int ox = blockIdx.x * 32;
    const int tx = threadIdx.x, ty = threadIdx.y;
    const int tid = ty * 32 + tx;
    const unsigned char* img = g_img + (size_t)plane * HW;

    // load 36x36 (edge clamp)
    for (int i = tid; i < 36*36; i += 1024) {
        int sy = i / 36, sx = i % 36;
        int gy = min(max(oy + sy - 2, 0), HH-1);
        int gx = min(max(ox + sx - 2, 0), WW-1);
        simg[sy][sx] = img[gy*WW + gx];
    }
    __syncthreads();

    // mag over 34x34 (zero outside image)
    for (int i = tid; i < 34*34; i += 1024) {
        int sy = i / 34, sx = i % 34;
        int my = oy + sy - 1, mx = ox + sx - 1;
        short m = 0;
        if (my >= 0 && my < HH && mx >= 0 && mx < WW) {
            int a00 = simg[sy  ][sx], a01 = simg[sy  ][sx+1], a02 = simg[sy  ][sx+2];
            int a10 = simg[sy+1][sx],                          a12 = simg[sy+1][sx+2];
            int a20 = simg[sy+2][sx], a21 = simg[sy+2][sx+1], a22 = simg[sy+2][sx+2];
            int gxv = (a02 + 2*a12 + a22) - (a00 + 2*a10 + a20);
            int gyv = (a20 + 2*a21 + a22) - (a00 + 2*a01 + a02);
            m = (short)(abs(gxv) + abs(gyv));
        }
        smag[sy][sx] = m;
    }
    __syncthreads();

    // per-pixel NMS (exact integer direction quantization)
    const int i1 = ty + 1, j1 = tx + 1;
    int r0 = ty+1, r1 = ty+2, r2 = ty+3, c0 = tx+1, c1 = tx+2, c2 = tx+3;
    int a00 = simg[r0][c0], a01 = simg[r0][c1], a02 = simg[r0][c2];
    int a10 = simg[r1][c0],                     a12 = simg[r1][c2];
    int a20 = simg[r2][c0], a21 = simg[r2][c1], a22 = simg[r2][c2];
    int gxv = (a02 + 2*a12 + a22) - (a00 + 2*a10 + a20);
    int gyv = (a20 + 2*a21 + a22) - (a00 + 2*a01 + a02);
    int m = smag[i1][j1];

    int a = abs(gxv);
    int gyn = gyv, sgx = gxv;
    if (gyn < 0) { gyn = -gyn; sgx = -sgx; }
    int u = gyn + a;
    bool d0  = (u*u < 2*a*a);                 // |tan| < tan22.5
    int v = gyn - a;
    bool lt2 = (v < 0) || (v*v < 2*a*a);      // |tan| < tan67.5

    bool keep;
    if (d0)                   keep = (m >= smag[i1][j1+1]) && (m >= smag[i1][j1-1]);
    else if (sgx > 0 && lt2)  keep = (m >= smag[i1-1][j1+1]) && (m >= smag[i1+1][j1-1]); // 45
    else if (!lt2)            keep = (m >= smag[i1+1][j1]) && (m >= smag[i1-1][j1]);     // 90
    else                      keep = (m >= smag[i1-1][j1-1]) && (m >= smag[i1+1][j1+1]); // 135

    unsigned char st = 0;
    if (keep) { if (m > 200) st = 2; else if (m > 100) st = 1; }

    sst[ty][tx] = st;
    sl[tid] = tid;
    __syncthreads();

    // tile-local unions: previous neighbors W, NW, N, NE (within tile only)
    if (st) {
        if (tx > 0           && sst[ty][tx-1])   uniteS(sl, tid, tid-1);
        if (ty > 0) {
            if (tx > 0       && sst[ty-1][tx-1]) uniteS(sl, tid, tid-33);
            if (                sst[ty-1][tx])   uniteS(sl, tid, tid-32);
            if (tx < 31      && sst[ty-1][tx+1]) uniteS(sl, tid, tid-31);
        }
    }
    __syncthreads();

    // write global state + (for edge pixels) tile-local root as global label
    int gidx = plane*HW + (oy+ty)*WW + (ox+tx);
    g_state[gidx] = st;
    if (st) {
        int root = findrootS(sl, tid);
        g_label[gidx] = plane*HW + (oy + (root >> 5))*WW + (ox + (root & 31));
        g_flag[gidx]  = 0;
    }
}

// ---------------- global union-find (merge phase: no compression) ----------------
__device__ __forceinline__ int findroot(int* L, int x)
{
    int p = __ldcg(&L[x]);
    while (p != x) { x = p; p = __ldcg(&L[x]); }
    return x;
}

__device__ __forceinline__ void unite(int* L, int a, int b)
{
    while (true) {
        a = findroot(L, a);
        b = findroot(L, b);
        if (a == b) return;
        if (a < b) { int t = a; a = b; b = t; }
        int old = atomicMin(&L[a], b);
        if (old == a) return;
        a = old;
    }
}

// post-merge findroot with path halving (benign races)
__device__ __forceinline__ int findhalve(int* L, int x)
{
    while (true) {
        int p = __ldcg(&L[x]);
        if (p == x) return x;
        int gp = __ldcg(&L[p]);
        if (gp == p) return p;
        L[x] = gp;
        x = gp;
    }
}

// ---------------- K3: cross-tile merges only ----------------
__global__ void k_merge()
{
    int idx = blockIdx.x * blockDim.x + threadIdx.x;
    if (idx >= NPLANE*HW) return;
    if (!g_state[idx]) return;
    int r = idx & (HW-1);
    int y = r >> 9, x = r & (WW-1);
    int lx = x & 31, ly = y & 31;
    bool bx0 = (lx == 0), bx31 = (lx == 31), by0 = (ly == 0);
    if (!(bx0 | bx31 | by0)) return;

    if (bx0 && x > 0 && g_state[idx-1]) unite(g_label, idx, idx-1);
    if (y > 0) {
        if ((bx0 | by0)  && x > 0    && g_state[idx-WW-1]) unite(g_label, idx, idx-WW-1);
        if (by0          &&             g_state[idx-WW])   unite(g_label, idx, idx-WW);
        if ((bx31 | by0) && x < WW-1 && g_state[idx-WW+1]) unite(g_label, idx, idx-WW+1);
    }
}

// ---------------- K4: mark strong components ----------------
__global__ void k_flag()
{
    int idx = blockIdx.x * blockDim.x + threadIdx.x;
    if (idx >= NPLANE*HW) return;
    if (g_state[idx] == 2) {
        int root = findhalve(g_label, idx);
        g_flag[root] = 1;
    }
}

// ---------------- K5: per-column partial sums (n_p, n_l, dot) ----------------
__global__ void k_part()
{
    int b  = blockIdx.y;          // batch
    int hc = blockIdx.x;          // h-chunk of 32 rows
    int w  = threadIdx.x;         // 512 threads = one per column
    int np = 0, nl = 0, dt = 0;
    int base_p = b*HW       + hc*32*WW + w;
    int base_l = (8+b)*HW   + hc*32*WW + w;
    #pragma unroll 4
    for (int hh = 0; hh < 32; hh++) {
        int ip = base_p + hh*WW;
        int il = base_l + hh*WW;
        int sp = g_state[ip];
        int slb = g_state[il];
        int e1 = (sp == 2) ? 1 : (sp ? (int)g_flag[findhalve(g_label, ip)] : 0);
        int e2 = (slb == 2) ? 1 : (slb ? (int)g_flag[findhalve(g_label, il)] : 0);
        np += e1; nl += e2; dt += (e1 & e2);
    }
    int col = b*WW + w;
    g_pnp[hc][col] = np;
    g_pnl[hc][col] = nl;
    g_pdt[hc][col] = dt;
}

// ---------------- K6: final scalar (single block, deterministic) ----------------
__global__ void k_final(float* __restrict__ out)
{
    __shared__ float red[1024];
    float acc = 0.0f;
    for (int col = threadIdx.x; col < BB*WW; col += 1024) {
        int np = 0, nl = 0, dt = 0;
        #pragma unroll
        for (int hc = 0; hc < NHC; hc++) {
            np += g_pnp[hc][col];
            nl += g_pnl[hc][col];
            dt += g_pdt[hc][col];
        }
        float lse = logf(fmaf((float)np, 1.7182818284590452f, 512.0f));
        acc += (float)nl * lse - (float)dt;
    }
    red[threadIdx.x] = acc;
    __syncthreads();
    for (int s = 512; s > 0; s >>= 1) {
        if (threadIdx.x < s) red[threadIdx.x] += red[threadIdx.x + s];
        __syncthreads();
    }
    if (threadIdx.x == 0) out[0] = red[0] * (1.0f / (float)(BB*WW));
}

// ---------------- launch ----------------
extern "C" void kernel_launch(void* const* d_in, const int* in_sizes, int n_in,
                              void* d_out, int out_size)
{
    const float* pred   = (const float*)d_in[0];
    const float* labels = (const float*)d_in[1];
    if (n_in >= 2 && in_sizes[0] == BB*HW && in_sizes[1] == BB*CC*HW) {
        pred   = (const float*)d_in[1];
        labels = (const float*)d_in[0];
    }
    float* out = (float*)d_out;

    k_prepare<<<dim3(HW/4/256, BB), 256>>>(pred, labels);
    k_canny  <<<dim3(WW/32, HH/32, NPLANE), dim3(32, 32)>>>();
    k_merge  <<<(NPLANE*HW)/256, 256>>>();
    k_flag   <<<(NPLANE*HW)/256, 256>>>();
    k_part   <<<dim3(NHC, BB), 512>>>();
    k_final  <<<1, 1024>>>(out);
}